// round 6
// baseline (speedup 1.0000x reference)
#include <cuda_runtime.h>

#define NSEG 128
#define KC   64
#define BZD  64

constexpr int PIX = 16;                               // consecutive y pixels per thread
constexpr int NW = 4;                                 // warps per block (K split 4 ways)
constexpr int THREADS = 32 * NW;                      // 128
constexpr int TPR = BZD / PIX;                        // 4 threads per row
constexpr int ROWS_PER_BLOCK = 32 / TPR;              // 8
constexpr int TILES_PER_SEG = BZD / ROWS_PER_BLOCK;   // 8
constexpr int NPAIR = PIX / 2;                        // 8
constexpr int KQ = KC / NW;                           // 16 components per warp

typedef unsigned long long u64;

__device__ __forceinline__ float ex2f(float x) {
    float r; asm("ex2.approx.ftz.f32 %0, %1;" : "=f"(r) : "f"(x)); return r;
}
__device__ __forceinline__ float rcpf(float x) {
    float r; asm("rcp.approx.ftz.f32 %0, %1;" : "=f"(r) : "f"(x)); return r;
}
__device__ __forceinline__ u64 pk2(float lo, float hi) {
    u64 r; asm("mov.b64 %0, {%1,%2};" : "=l"(r) : "f"(lo), "f"(hi)); return r;
}
__device__ __forceinline__ void upk2(float& lo, float& hi, u64 v) {
    asm("mov.b64 {%0,%1}, %2;" : "=f"(lo), "=f"(hi) : "l"(v));
}
__device__ __forceinline__ u64 fma2(u64 a, u64 b, u64 c) {
    u64 r; asm("fma.rn.f32x2 %0, %1, %2, %3;" : "=l"(r) : "l"(a), "l"(b), "l"(c)); return r;
}
__device__ __forceinline__ u64 add2(u64 a, u64 b) {
    u64 r; asm("add.rn.f32x2 %0, %1, %2;" : "=l"(r) : "l"(a), "l"(b)); return r;
}
__device__ __forceinline__ u64 mul2(u64 a, u64 b) {
    u64 r; asm("mul.rn.f32x2 %0, %1, %2;" : "=l"(r) : "l"(a), "l"(b)); return r;
}

__global__ __launch_bounds__(THREADS)
void seg_splat_kernel(const float* __restrict__ u,
                      const float* __restrict__ a,
                      const float* __restrict__ B,
                      float* __restrict__ out)
{
    __shared__ float4 sK1[KC];              // {A', Bc', ux, uy}
    __shared__ float4 sK2[KC];              // {C', 2C'h, gamma, s2}
    __shared__ float4 sK3[KC];              // {s4, g64, g17, s32}
    __shared__ u64    sK4[KC][2];           // {a,a}, {s8,s8}
    __shared__ u64    sNum[NW][NPAIR][32];  // per-warp partials
    __shared__ u64    sDen[NW][NPAIR][32];

    const int n    = blockIdx.x / TILES_PER_SEG;
    const int tile = blockIdx.x % TILES_PER_SEG;
    const int tid  = threadIdx.x;
    const int lane = tid & 31;
    const int wid  = tid >> 5;              // which K quarter

    const float h = 1.0f / BZD;

    // Per-component constants: one k per thread for tid < KC
    if (tid < KC) {
        const int k = tid;
        const float* bp = B + (size_t)(n * KC + k) * 4;
        float b00 = bp[0], b10 = bp[2], b11 = bp[3];
        const float L = -0.72134752044448170368f;   // -0.5 * log2(e)
        float A  = L * (b00 * b00 + b10 * b10);
        float Bc = 2.0f * L * (b10 * b11);
        float C  = L * (b11 * b11);
        float gamma = C * (h * h);                  // log2-domain per-pixel-step quadratic
        float s2 = ex2f(2.0f * gamma);
        float s4 = s2 * s2;
        float s8 = s4 * s4;
        float s16 = s8 * s8;
        float s32 = s16 * s16;                      // 2^(32*gamma)
        const float* up = u + (size_t)(n * KC + k) * 2;
        float av = a[n * KC + k];
        sK1[k] = make_float4(A, Bc, up[0], up[1]);
        sK2[k] = make_float4(C, 2.0f * C * h, gamma, s2);
        sK3[k] = make_float4(s4, 64.0f * gamma, 17.0f * gamma, s32);
        sK4[k][0] = pk2(av, av);
        sK4[k][1] = pk2(s8, s8);
    }
    __syncthreads();

    const int row = lane / TPR;
    const int j0  = (lane % TPR) * PIX;
    const int i   = tile * ROWS_PER_BLOCK + row;

    const float xi = ((float)i  + 0.5f) * h;
    const float y0 = ((float)j0 + 0.5f) * h;

    u64 num2[NPAIR], den2[NPAIR];
    const u64 zz = pk2(0.0f, 0.0f);
#pragma unroll
    for (int p = 0; p < NPAIR; p++) { num2[p] = zz; den2[p] = zz; }

    const int kbeg = wid * KQ;
    const float4* p1 = sK1 + kbeg;
    const float4* p2 = sK2 + kbeg;
    const float4* p3 = sK3 + kbeg;
    const u64*    p4 = &sK4[kbeg][0];

#pragma unroll 2
    for (int kk = 0; kk < KQ; kk++) {
        float4 k1 = p1[kk];
        float4 k2 = p2[kk];
        float4 k3 = p3[kk];
        u64 a2   = p4[2 * kk];
        u64 s8_2 = p4[2 * kk + 1];

        float dx  = xi - k1.z;
        float dy0 = y0 - k1.w;
        float bdx = k1.y * dx;                        // Bc'*dx
        float adx = k1.x * dx;                        // A'*dx
        float t3  = fmaf(k2.x, dy0, bdx);             // C'*dy0 + Bc'*dx
        float E0  = fmaf(dy0, t3, adx * dx);          // exponent at t=0 (log2 domain)
        float beta = fmaf(k2.y, dy0, bdx * h);        // h*(Bc'dx + 2C'dy0)
        float bpg = beta + k2.z;                      // beta + gamma
        float E8  = fmaf(beta, 8.0f, E0) + k3.y;      // E0 + 8b + 64g
        float E9  = (E8 + beta) + k3.z;               // E8 + b + 17g

        float kv0 = ex2f(E0);
        float w   = ex2f(bpg);
        float kv8 = ex2f(E8);
        float kv9 = ex2f(E9);

        float kv1 = kv0 * w;
        float w2  = w * w;
        float rlo = w2 * k2.w;                        // 2^(2b+4g)
        float rhi = rlo * k3.x;                       // 2^(2b+8g)
        float r4lo = rlo * k3.w;                      // 2^(2b+36g)
        float r4hi = rhi * k3.w;                      // 2^(2b+40g)

        u64 kvA = pk2(kv0, kv1);                      // pairs 0..3
        u64 rA  = pk2(rlo, rhi);
        u64 kvB = pk2(kv8, kv9);                      // pairs 4..7
        u64 rB  = pk2(r4lo, r4hi);

#pragma unroll
        for (int p = 0; p < 4; p++) {
            den2[p]     = add2(den2[p], kvA);
            num2[p]     = fma2(a2, kvA, num2[p]);
            den2[p + 4] = add2(den2[p + 4], kvB);
            num2[p + 4] = fma2(a2, kvB, num2[p + 4]);
            if (p < 3) {
                kvA = mul2(kvA, rA);
                rA  = mul2(rA, s8_2);
                kvB = mul2(kvB, rB);
                rB  = mul2(rB, s8_2);
            }
        }
    }

    // All warps publish partials
#pragma unroll
    for (int p = 0; p < NPAIR; p++) {
        sNum[wid][p][lane] = num2[p];
        sDen[wid][p][lane] = den2[p];
    }
    __syncthreads();

    // Warp w reduces pixel-pairs {2w, 2w+1}: pixels [4w, 4w+4) of each strip
    float res[4];
#pragma unroll
    for (int q = 0; q < 2; q++) {
        const int p = 2 * wid + q;
        u64 nt = add2(add2(sNum[0][p][lane], sNum[1][p][lane]),
                      add2(sNum[2][p][lane], sNum[3][p][lane]));
        u64 dt = add2(add2(sDen[0][p][lane], sDen[1][p][lane]),
                      add2(sDen[2][p][lane], sDen[3][p][lane]));
        float n0, n1, d0, d1;
        upk2(n0, n1, nt);
        upk2(d0, d1, dt);
        res[2 * q]     = n0 * rcpf(fmaxf(d0, 1e-7f));
        res[2 * q + 1] = n1 * rcpf(fmaxf(d1, 1e-7f));
    }
    float4* op = (float4*)(out + (size_t)n * (BZD * BZD) + (size_t)i * BZD + j0 + 4 * wid);
    op[0] = ((float4*)res)[0];
}

extern "C" void kernel_launch(void* const* d_in, const int* in_sizes, int n_in,
                              void* d_out, int out_size)
{
    const float* u = (const float*)d_in[0];
    const float* a = (const float*)d_in[1];
    const float* B = (const float*)d_in[2];
    float* out     = (float*)d_out;

    int blocks = NSEG * TILES_PER_SEG;   // 1024 blocks x 4 warps
    seg_splat_kernel<<<blocks, THREADS>>>(u, a, B, out);
}

// round 7
// speedup vs baseline: 1.2411x; 1.2411x over previous
#include <cuda_runtime.h>

#define NSEG 128
#define KC   64
#define BZD  64

constexpr int PIX = 16;                               // consecutive y pixels per thread
constexpr int NW = 4;                                 // warps per block (K split 4 ways)
constexpr int THREADS = 32 * NW;                      // 128
constexpr int TPR = BZD / PIX;                        // 4 threads per row
constexpr int ROWS_PER_BLOCK = 32 / TPR;              // 8
constexpr int TILES_PER_SEG = BZD / ROWS_PER_BLOCK;   // 8
constexpr int NPAIR = PIX / 2;                        // 8
constexpr int KQ = KC / NW;                           // 16 components per warp
constexpr int JQ = KQ / 2;                            // 8 k-pairs per warp

typedef unsigned long long u64;

__device__ __forceinline__ float ex2f(float x) {
    float r; asm("ex2.approx.ftz.f32 %0, %1;" : "=f"(r) : "f"(x)); return r;
}
__device__ __forceinline__ float rcpf(float x) {
    float r; asm("rcp.approx.ftz.f32 %0, %1;" : "=f"(r) : "f"(x)); return r;
}
__device__ __forceinline__ u64 pk2(float lo, float hi) {
    u64 r; asm("mov.b64 %0, {%1,%2};" : "=l"(r) : "f"(lo), "f"(hi)); return r;
}
__device__ __forceinline__ void upk2(float& lo, float& hi, u64 v) {
    asm("mov.b64 {%0,%1}, %2;" : "=f"(lo), "=f"(hi) : "l"(v));
}
__device__ __forceinline__ u64 fma2(u64 a, u64 b, u64 c) {
    u64 r; asm("fma.rn.f32x2 %0, %1, %2, %3;" : "=l"(r) : "l"(a), "l"(b), "l"(c)); return r;
}
__device__ __forceinline__ u64 add2(u64 a, u64 b) {
    u64 r; asm("add.rn.f32x2 %0, %1, %2;" : "=l"(r) : "l"(a), "l"(b)); return r;
}
__device__ __forceinline__ u64 mul2(u64 a, u64 b) {
    u64 r; asm("mul.rn.f32x2 %0, %1, %2;" : "=l"(r) : "l"(a), "l"(b)); return r;
}

__global__ __launch_bounds__(THREADS)
void seg_splat_kernel(const float* __restrict__ u,
                      const float* __restrict__ a,
                      const float* __restrict__ B,
                      float* __restrict__ out)
{
    // k-pair-packed constants: entry j covers components {2j, 2j+1} (lanes a,b)
    __shared__ ulonglong2 sPA[KC / 2];       // { {-uxa,-uxb}, {-uya,-uyb} }
    __shared__ ulonglong2 sPB[KC / 2];       // { {Aa,Ab},     {Bca,Bcb}   }
    __shared__ ulonglong2 sPC[KC / 2];       // { {Ca,Cb},     {2Cha,2Chb} }
    __shared__ ulonglong2 sPD[KC / 2];       // { {ga,gb},     {s2a,s2b}   }
    __shared__ u64        sS4[KC / 2];       // {s4a, s4b}
    __shared__ ulonglong2 sQ[KC];            // per-k: { {a,a}, {s8,s8} }
    __shared__ u64 sNum[NW][NPAIR][32];      // per-warp partials
    __shared__ u64 sDen[NW][NPAIR][32];

    const int n    = blockIdx.x / TILES_PER_SEG;
    const int tile = blockIdx.x % TILES_PER_SEG;
    const int tid  = threadIdx.x;
    const int lane = tid & 31;
    const int wid  = tid >> 5;               // which K quarter

    const float h = 1.0f / BZD;

    // Per-component constants: one k per thread for tid < KC
    if (tid < KC) {
        const int k = tid;
        const int j = k >> 1;
        const int b = k & 1;
        const float* bp = B + (size_t)(n * KC + k) * 4;
        float b00 = bp[0], b10 = bp[2], b11 = bp[3];
        const float L = -0.72134752044448170368f;   // -0.5 * log2(e)
        float A  = L * (b00 * b00 + b10 * b10);
        float Bc = 2.0f * L * (b10 * b11);
        float C  = L * (b11 * b11);
        float gamma = C * (h * h);
        float s2 = ex2f(2.0f * gamma);
        float s4 = s2 * s2;
        float s8 = s4 * s4;
        const float* up = u + (size_t)(n * KC + k) * 2;
        float av = a[n * KC + k];

        ((float*)&sPA[j])[b]     = -up[0];
        ((float*)&sPA[j])[2 + b] = -up[1];
        ((float*)&sPB[j])[b]     = A;
        ((float*)&sPB[j])[2 + b] = Bc;
        ((float*)&sPC[j])[b]     = C;
        ((float*)&sPC[j])[2 + b] = 2.0f * C * h;
        ((float*)&sPD[j])[b]     = gamma;
        ((float*)&sPD[j])[2 + b] = s2;
        ((float*)&sS4[j])[b]     = s4;
        sQ[k].x = pk2(av, av);
        sQ[k].y = pk2(s8, s8);
    }
    __syncthreads();

    const int row = lane / TPR;
    const int j0  = (lane % TPR) * PIX;
    const int i   = tile * ROWS_PER_BLOCK + row;

    const float xi = ((float)i  + 0.5f) * h;
    const float y0 = ((float)j0 + 0.5f) * h;
    const u64 xi2 = pk2(xi, xi);
    const u64 y02 = pk2(y0, y0);
    const u64 h2  = pk2(h, h);

    u64 num2[NPAIR], den2[NPAIR];
    const u64 zz = pk2(0.0f, 0.0f);
#pragma unroll
    for (int p = 0; p < NPAIR; p++) { num2[p] = zz; den2[p] = zz; }

    const int jbeg = wid * JQ;
#pragma unroll 1
    for (int jj = jbeg; jj < jbeg + JQ; jj++) {
        ulonglong2 pa = sPA[jj];
        ulonglong2 pb = sPB[jj];
        ulonglong2 pc = sPC[jj];
        ulonglong2 pd = sPD[jj];
        u64 s4_2 = sS4[jj];

        // packed-across-k prologue (lanes = components 2jj, 2jj+1)
        u64 dx2   = add2(xi2, pa.x);
        u64 dy2   = add2(y02, pa.y);
        u64 bdx2  = mul2(pb.y, dx2);             // Bc'*dx
        u64 adx2  = mul2(pb.x, dx2);             // A'*dx
        u64 t32   = fma2(pc.x, dy2, bdx2);       // C'*dy0 + Bc'*dx
        u64 axx2  = mul2(adx2, dx2);
        u64 E02   = fma2(dy2, t32, axx2);        // exponent at t=0 (log2)
        u64 bh2   = mul2(bdx2, h2);
        u64 beta2 = fma2(pc.y, dy2, bh2);        // h*(Bc'dx + 2C'dy0)
        u64 bpg2  = add2(beta2, pd.x);           // beta + gamma

        float e0a, e0b, bga, bgb;
        upk2(e0a, e0b, E02);
        upk2(bga, bgb, bpg2);
        float kv0a = ex2f(e0a), kv0b = ex2f(e0b);
        float wa   = ex2f(bga), wb   = ex2f(bgb);

        u64 kv0_2 = pk2(kv0a, kv0b);
        u64 w_2   = pk2(wa, wb);
        u64 kv1_2 = mul2(kv0_2, w_2);
        u64 ww2   = mul2(w_2, w_2);
        u64 rlo2  = mul2(ww2, pd.y);             // 2^(2b+4g) per k
        u64 rhi2  = mul2(rlo2, s4_2);            // 2^(2b+8g) per k

        // repack to per-k pixel-pair chains (movs, alu pipe)
        float kv1a, kv1b, rloa, rlob, rhia, rhib;
        upk2(kv1a, kv1b, kv1_2);
        upk2(rloa, rlob, rlo2);
        upk2(rhia, rhib, rhi2);
        u64 kvA = pk2(kv0a, kv1a);
        u64 kvB = pk2(kv0b, kv1b);
        u64 rA  = pk2(rloa, rhia);
        u64 rB  = pk2(rlob, rhib);

        ulonglong2 qa = sQ[2 * jj];
        ulonglong2 qb = sQ[2 * jj + 1];

        // two independent k-chains interleaved
#pragma unroll
        for (int p = 0; p < NPAIR; p++) {
            den2[p] = add2(den2[p], kvA);
            num2[p] = fma2(qa.x, kvA, num2[p]);
            den2[p] = add2(den2[p], kvB);
            num2[p] = fma2(qb.x, kvB, num2[p]);
            if (p < NPAIR - 1) {
                kvA = mul2(kvA, rA);
                rA  = mul2(rA, qa.y);
                kvB = mul2(kvB, rB);
                rB  = mul2(rB, qb.y);
            }
        }
    }

    // All warps publish partials
#pragma unroll
    for (int p = 0; p < NPAIR; p++) {
        sNum[wid][p][lane] = num2[p];
        sDen[wid][p][lane] = den2[p];
    }
    __syncthreads();

    // Warp w reduces pixel-pairs {2w, 2w+1}: pixels [4w, 4w+4) of each strip
    float res[4];
#pragma unroll
    for (int q = 0; q < 2; q++) {
        const int p = 2 * wid + q;
        u64 nt = add2(add2(sNum[0][p][lane], sNum[1][p][lane]),
                      add2(sNum[2][p][lane], sNum[3][p][lane]));
        u64 dt = add2(add2(sDen[0][p][lane], sDen[1][p][lane]),
                      add2(sDen[2][p][lane], sDen[3][p][lane]));
        float n0, n1, d0, d1;
        upk2(n0, n1, nt);
        upk2(d0, d1, dt);
        res[2 * q]     = n0 * rcpf(fmaxf(d0, 1e-7f));
        res[2 * q + 1] = n1 * rcpf(fmaxf(d1, 1e-7f));
    }
    float4* op = (float4*)(out + (size_t)n * (BZD * BZD) + (size_t)i * BZD + j0 + 4 * wid);
    op[0] = ((float4*)res)[0];
}

extern "C" void kernel_launch(void* const* d_in, const int* in_sizes, int n_in,
                              void* d_out, int out_size)
{
    const float* u = (const float*)d_in[0];
    const float* a = (const float*)d_in[1];
    const float* B = (const float*)d_in[2];
    float* out     = (float*)d_out;

    int blocks = NSEG * TILES_PER_SEG;   // 1024 blocks x 4 warps
    seg_splat_kernel<<<blocks, THREADS>>>(u, a, B, out);
}